// round 13
// baseline (speedup 1.0000x reference)
#include <cuda_runtime.h>
#include <cuda_bf16.h>
#include <cstdint>

#define B_ 4
#define T_ 2048
#define H_ 2048
#define F_ 8192
#define M_ (B_*T_)   // 8192 tokens

// ---------------- device scratch (static; no allocations) ----------------
__device__ __nv_bfloat16 g_wkq[(size_t)F_*H_];   // ternary key weight codes
__device__ __nv_bfloat16 g_wrq[(size_t)H_*H_];   // ternary receptance weight codes
__device__ __nv_bfloat16 g_wvq[(size_t)H_*F_];   // ternary value weight codes
__device__ __nv_bfloat16 g_aK[(size_t)M_*H_];    // int8 codes of key_in (as bf16)
__device__ __nv_bfloat16 g_aR[(size_t)M_*H_];    // int8 codes of rec_in
__device__ __nv_bfloat16 g_aV[(size_t)M_*F_];    // int8 codes of k
__device__ float g_kraw[(size_t)M_*F_];          // k = relu(.)^2, fp32
__device__ float g_rbuf[(size_t)M_*H_];          // sigmoid(receptance)
__device__ float g_sK[M_], g_sR[M_], g_sV[M_];   // per-row dequant scale
__device__ float g_part[3*1024];
__device__ float g_wdeq[3];                      // per-tensor dequant scale (1/ws)

// ---------------- reductions ----------------
__device__ __forceinline__ float warpSum(float v){
  #pragma unroll
  for(int o=16;o;o>>=1) v += __shfl_xor_sync(0xffffffffu, v, o);
  return v;
}
__device__ __forceinline__ float warpMax(float v){
  #pragma unroll
  for(int o=16;o;o>>=1) v = fmaxf(v, __shfl_xor_sync(0xffffffffu, v, o));
  return v;
}
__device__ __forceinline__ float blkSum(float v, float* sm){
  int t = threadIdx.x, nw = blockDim.x >> 5;
  v = warpSum(v);
  if((t&31)==0) sm[t>>5] = v;
  __syncthreads();
  float r = (t < nw) ? sm[t] : 0.f;
  r = warpSum(r);
  if(t==0) sm[0] = r;
  __syncthreads();
  r = sm[0];
  __syncthreads();
  return r;
}
__device__ __forceinline__ float blkMax(float v, float* sm){
  int t = threadIdx.x, nw = blockDim.x >> 5;
  v = warpMax(v);
  if((t&31)==0) sm[t>>5] = v;
  __syncthreads();
  float r = (t < nw) ? sm[t] : 0.f;
  r = warpMax(r);
  if(t==0) sm[0] = r;
  __syncthreads();
  r = sm[0];
  __syncthreads();
  return r;
}

// ---------------- weight |w| partial sums: all 3 weights in one launch ----------------
__global__ void k_absum_all(const float* __restrict__ wk, const float* __restrict__ wr,
                            const float* __restrict__ wv){
  __shared__ float sm[32];
  int region = blockIdx.x >> 10;           // 0..2
  int lb     = blockIdx.x & 1023;
  const float* w = (region==0) ? wk : (region==1) ? wr : wv;
  int n4 = (region==0) ? (F_*H_)/4 : (region==1) ? (H_*H_)/4 : (H_*F_)/4;
  float s = 0.f;
  const float4* w4 = (const float4*)w;
  for(int i = lb*blockDim.x + threadIdx.x; i < n4; i += 1024*blockDim.x){
    float4 v = w4[i];
    s += fabsf(v.x) + fabsf(v.y) + fabsf(v.z) + fabsf(v.w);
  }
  s = blkSum(s, sm);
  if(threadIdx.x == 0) g_part[region*1024 + lb] = s;
}

// ---------------- fused: ternary weight quant + token-shift/RMSNorm act quant -------
// blocks [0, 9216): weight quant; blocks [9216, 9216+M_): actprep (vectorized)
__global__ void k_prep_all(const float* __restrict__ wk, const float* __restrict__ wr,
                           const float* __restrict__ wv,
                           const float* __restrict__ hidden,
                           const float* __restrict__ tmk, const float* __restrict__ tmr,
                           const float* __restrict__ nk,  const float* __restrict__ nr){
  __shared__ float sm[32];
  int b = blockIdx.x;
  if(b < 9216){
    int region, lb, nblk;
    if(b < 4096){ region=0; lb=b; nblk=4096; }
    else if(b < 5120){ region=1; lb=b-4096; nblk=1024; }
    else { region=2; lb=b-5120; nblk=4096; }
    const float* w = (region==0) ? wk : (region==1) ? wr : wv;
    __nv_bfloat16* wq = (region==0) ? g_wkq : (region==1) ? g_wrq : g_wvq;
    int n4 = (region==0) ? (F_*H_)/4 : (region==1) ? (H_*H_)/4 : (H_*F_)/4;
    float cnt = (float)((size_t)n4*4);

    float p = 0.f;
    #pragma unroll
    for(int j=0;j<4;j++) p += g_part[region*1024 + threadIdx.x + j*256];
    float tot = blkSum(p, sm);
    float wdeq = fmaxf(tot/cnt, 1e-5f);
    float ws = 1.f / wdeq;
    if(lb == 0 && threadIdx.x == 0) g_wdeq[region] = wdeq;

    for(int i = lb*blockDim.x + threadIdx.x; i < n4; i += nblk*blockDim.x){
      float4 v = ((const float4*)w)[i];
      float q0 = fminf(fmaxf(rintf(v.x*ws), -1.f), 1.f);
      float q1 = fminf(fmaxf(rintf(v.y*ws), -1.f), 1.f);
      float q2 = fminf(fmaxf(rintf(v.z*ws), -1.f), 1.f);
      float q3 = fminf(fmaxf(rintf(v.w*ws), -1.f), 1.f);
      __nv_bfloat162* o = ((__nv_bfloat162*)wq) + 2*(size_t)i;
      o[0] = __floats2bfloat162_rn(q0, q1);
      o[1] = __floats2bfloat162_rn(q2, q3);
    }
  } else {
    int m = b - 9216;
    int t = m & (T_-1);
    const float4* cur  = (const float4*)(hidden + (size_t)m*H_);
    const float4* tmk4 = (const float4*)tmk;
    const float4* tmr4 = (const float4*)tmr;
    const float4* nk4  = (const float4*)nk;
    const float4* nr4  = (const float4*)nr;
    const int base = threadIdx.x*2;                 // 2 float4 = 8 contiguous elems
    float4 kin[2], rin[2];
    float ssk=0.f, ssr=0.f, amk=0.f, amr=0.f;
    #pragma unroll
    for(int j=0;j<2;j++){
      float4 xc = cur[base+j];
      float4 xp = (t==0) ? make_float4(0.f,0.f,0.f,0.f) : cur[base+j - H_/4];
      float4 a = tmk4[base+j], bb = tmr4[base+j];
      float4 wkv = nk4[base+j], wrv = nr4[base+j];
      float4 ki, ri;
      ki.x = xc.x*a.x + xp.x*(1.f-a.x);  ki.y = xc.y*a.y + xp.y*(1.f-a.y);
      ki.z = xc.z*a.z + xp.z*(1.f-a.z);  ki.w = xc.w*a.w + xp.w*(1.f-a.w);
      ri.x = xc.x*bb.x + xp.x*(1.f-bb.x); ri.y = xc.y*bb.y + xp.y*(1.f-bb.y);
      ri.z = xc.z*bb.z + xp.z*(1.f-bb.z); ri.w = xc.w*bb.w + xp.w*(1.f-bb.w);
      kin[j]=ki; rin[j]=ri;
      ssk += ki.x*ki.x + ki.y*ki.y + ki.z*ki.z + ki.w*ki.w;
      ssr += ri.x*ri.x + ri.y*ri.y + ri.z*ri.z + ri.w*ri.w;
      amk = fmaxf(amk, fmaxf(fmaxf(fabsf(ki.x*wkv.x), fabsf(ki.y*wkv.y)),
                             fmaxf(fabsf(ki.z*wkv.z), fabsf(ki.w*wkv.w))));
      amr = fmaxf(amr, fmaxf(fmaxf(fabsf(ri.x*wrv.x), fabsf(ri.y*wrv.y)),
                             fmaxf(fabsf(ri.z*wrv.z), fabsf(ri.w*wrv.w))));
    }
    float tssk = blkSum(ssk, sm);
    float tssr = blkSum(ssr, sm);
    float tamk = blkMax(amk, sm);
    float tamr = blkMax(amr, sm);
    float rk = rsqrtf(tssk*(1.f/H_) + 1e-8f);
    float rr = rsqrtf(tssr*(1.f/H_) + 1e-8f);
    float rsK = fmaxf(tamk*rk, 1e-5f);
    float rsR = fmaxf(tamr*rr, 1e-5f);
    float sk = 127.f/rsK, sr = 127.f/rsR;
    uint32_t pk[4], pr[4];
    #pragma unroll
    for(int j=0;j<2;j++){
      float4 wkv = nk4[base+j], wrv = nr4[base+j];
      float4 ki = kin[j], ri = rin[j];
      float qk0 = fminf(fmaxf(rintf(ki.x*wkv.x*rk*sk), -128.f), 127.f);
      float qk1 = fminf(fmaxf(rintf(ki.y*wkv.y*rk*sk), -128.f), 127.f);
      float qk2 = fminf(fmaxf(rintf(ki.z*wkv.z*rk*sk), -128.f), 127.f);
      float qk3 = fminf(fmaxf(rintf(ki.w*wkv.w*rk*sk), -128.f), 127.f);
      float qr0 = fminf(fmaxf(rintf(ri.x*wrv.x*rr*sr), -128.f), 127.f);
      float qr1 = fminf(fmaxf(rintf(ri.y*wrv.y*rr*sr), -128.f), 127.f);
      float qr2 = fminf(fmaxf(rintf(ri.z*wrv.z*rr*sr), -128.f), 127.f);
      float qr3 = fminf(fmaxf(rintf(ri.w*wrv.w*rr*sr), -128.f), 127.f);
      __nv_bfloat162 k01 = __floats2bfloat162_rn(qk0, qk1);
      __nv_bfloat162 k23 = __floats2bfloat162_rn(qk2, qk3);
      __nv_bfloat162 r01 = __floats2bfloat162_rn(qr0, qr1);
      __nv_bfloat162 r23 = __floats2bfloat162_rn(qr2, qr3);
      pk[2*j]   = *(uint32_t*)&k01;  pk[2*j+1] = *(uint32_t*)&k23;
      pr[2*j]   = *(uint32_t*)&r01;  pr[2*j+1] = *(uint32_t*)&r23;
    }
    *((uint4*)(g_aK + (size_t)m*H_) + threadIdx.x) = make_uint4(pk[0],pk[1],pk[2],pk[3]);
    *((uint4*)(g_aR + (size_t)m*H_) + threadIdx.x) = make_uint4(pr[0],pr[1],pr[2],pr[3]);
    if(threadIdx.x == 0){ g_sK[m] = rsK*(1.f/127.f); g_sR[m] = rsR*(1.f/127.f); }
  }
}

// ---------------- RMSNorm + int8 quant of k rows (F=8192), vectorized ----------------
__global__ void k_quantK(const float* __restrict__ nv){
  __shared__ float sm[32];
  int m = blockIdx.x;
  const float4* row = (const float4*)(g_kraw + (size_t)m*F_);
  const float4* nv4 = (const float4*)nv;
  float4 v[8];
  float ss=0.f, am=0.f;
  #pragma unroll
  for(int j=0;j<8;j++){
    float4 x = row[threadIdx.x + j*256];
    float4 n = nv4[threadIdx.x + j*256];
    v[j] = x;
    ss += x.x*x.x + x.y*x.y + x.z*x.z + x.w*x.w;
    am = fmaxf(am, fmaxf(fmaxf(fabsf(x.x*n.x), fabsf(x.y*n.y)),
                         fmaxf(fabsf(x.z*n.z), fabsf(x.w*n.w))));
  }
  float tss = blkSum(ss, sm);
  float tam = blkMax(am, sm);
  float rinv = rsqrtf(tss*(1.f/F_) + 1e-8f);
  float rs = fmaxf(tam*rinv, 1e-5f);
  float s = 127.f/rs;
  #pragma unroll
  for(int j=0;j<8;j++){
    float4 n = nv4[threadIdx.x + j*256];
    float4 x = v[j];
    float q0 = fminf(fmaxf(rintf(x.x*n.x*rinv*s), -128.f), 127.f);
    float q1 = fminf(fmaxf(rintf(x.y*n.y*rinv*s), -128.f), 127.f);
    float q2 = fminf(fmaxf(rintf(x.z*n.z*rinv*s), -128.f), 127.f);
    float q3 = fminf(fmaxf(rintf(x.w*n.w*rinv*s), -128.f), 127.f);
    __nv_bfloat162 c01 = __floats2bfloat162_rn(q0, q1);
    __nv_bfloat162 c23 = __floats2bfloat162_rn(q2, q3);
    uint2 pk = make_uint2(*(uint32_t*)&c01, *(uint32_t*)&c23);
    *((uint2*)(g_aV + (size_t)m*F_) + threadIdx.x + j*256) = pk;
  }
  if(threadIdx.x == 0) g_sV[m] = rs*(1.f/127.f);
}

// ---------------- bf16 tensor-core GEMM (R12 config, unchanged) ----------------
#define BM 128
#define BN 128
#define BKg 64          // 64 bf16 elems = 128 B per row
#define LDT 72          // elems: 64 + 8 pad -> 144B row stride, conflict-free
#define NSTAGE 3
#define NTHR 128
#define STAGE_E ((BM+BN)*LDT)           // elems per stage: 18432
#define STAGE_BYTES (STAGE_E*2)         // 36864 B
#define SMEM_TOTAL (NSTAGE*STAGE_BYTES) // 110592 B

__device__ __forceinline__ void cp16(uint32_t s, const void* g){
  asm volatile("cp.async.cg.shared.global [%0], [%1], 16;" :: "r"(s), "l"(g));
}
__device__ __forceinline__ void cp_commit(){ asm volatile("cp.async.commit_group;" ::: "memory"); }
template<int N> __device__ __forceinline__ void cp_wait(){
  asm volatile("cp.async.wait_group %0;" :: "n"(N) : "memory");
}
__device__ __forceinline__ void ldsm4(uint32_t& r0, uint32_t& r1, uint32_t& r2, uint32_t& r3,
                                      uint32_t addr){
  asm volatile("ldmatrix.sync.aligned.m8n8.x4.shared.b16 {%0,%1,%2,%3}, [%4];"
               : "=r"(r0), "=r"(r1), "=r"(r2), "=r"(r3) : "r"(addr));
}
__device__ __forceinline__ void mma16816(float* c, const uint32_t* a, const uint32_t* b){
  asm volatile(
    "mma.sync.aligned.m16n8k16.row.col.f32.bf16.bf16.f32 "
    "{%0,%1,%2,%3}, {%4,%5,%6,%7}, {%8,%9}, {%0,%1,%2,%3};\n"
    : "+f"(c[0]), "+f"(c[1]), "+f"(c[2]), "+f"(c[3])
    : "r"(a[0]), "r"(a[1]), "r"(a[2]), "r"(a[3]), "r"(b[0]), "r"(b[1]));
}

// Shared mainloop: computes acc for C[bm:bm+128, bn:bn+128] = A*Bw^T
template<int KDIM>
__device__ __forceinline__ void gemm_main(const __nv_bfloat16* __restrict__ A,
                                          const __nv_bfloat16* __restrict__ Bw,
                                          int bm, int bn,
                                          __nv_bfloat16* smem,
                                          float acc[4][8][4]){
  constexpr int NKT = KDIM / BKg;
  const int tid = threadIdx.x;

  auto loads = [&](int buf, int kt){
    __nv_bfloat16* st = smem + buf*STAGE_E;
    const __nv_bfloat16* Ak = A  + (size_t)bm*KDIM + kt*BKg;
    const __nv_bfloat16* Bk = Bw + (size_t)bn*KDIM + kt*BKg;
    #pragma unroll
    for(int i=0;i<16;i++){
      int chunk = tid + NTHR*i;        // 0..2047 : 256 rows x 8 x 16B
      int row = chunk >> 3;
      int kc  = (chunk & 7) << 3;      // elems: 0,8,...,56
      const __nv_bfloat16* gp = (row < BM) ? (Ak + (size_t)row*KDIM + kc)
                                           : (Bk + (size_t)(row-BM)*KDIM + kc);
      cp16((uint32_t)__cvta_generic_to_shared(st + row*LDT + kc), gp);
    }
    cp_commit();
  };

  const int warp = tid >> 5, lane = tid & 31;
  const int wm = (warp & 1) * 64;
  const int wn = (warp >> 1) * 64;

  const uint32_t sbu = (uint32_t)__cvta_generic_to_shared(smem);
  const int aoff = (wm + (lane & 15))*LDT + ((lane >> 4) << 3);
  const int boff = (wn + (lane & 7) + ((lane >> 4) << 3))*LDT + (((lane >> 3) & 1) << 3);

  loads(0, 0);
  loads(1, 1);

  #pragma unroll 1
  for(int kt=0; kt<NKT; kt++){
    cp_wait<NSTAGE-2>();
    __syncthreads();
    if(kt + NSTAGE - 1 < NKT) loads((kt + NSTAGE - 1) % NSTAGE, kt + NSTAGE - 1);
    else cp_commit();

    const int buf = kt % NSTAGE;
    const uint32_t abase = sbu + buf*STAGE_BYTES;
    const uint32_t bbase = abase + BM*LDT*2;

    // ks pairs: batch A-fragment ldsm for 2 ks steps (8 ldsm4 burst),
    // then per-ks B ldsm + mma
    #pragma unroll
    for(int kp=0; kp<2; kp++){
      uint32_t afr[2][4][4];
      #pragma unroll
      for(int ks2=0; ks2<2; ks2++){
        const int kk = (kp*2 + ks2)*16;
        #pragma unroll
        for(int mi=0; mi<4; mi++)
          ldsm4(afr[ks2][mi][0], afr[ks2][mi][1], afr[ks2][mi][2], afr[ks2][mi][3],
                abase + (uint32_t)(aoff + mi*16*LDT + kk)*2);
      }
      #pragma unroll
      for(int ks2=0; ks2<2; ks2++){
        const int kk = (kp*2 + ks2)*16;
        uint32_t bfr[8][2];
        #pragma unroll
        for(int nip=0; nip<4; nip++)
          ldsm4(bfr[2*nip][0], bfr[2*nip][1], bfr[2*nip+1][0], bfr[2*nip+1][1],
                bbase + (uint32_t)(boff + nip*16*LDT + kk)*2);
        #pragma unroll
        for(int mi=0; mi<4; mi++)
          #pragma unroll
          for(int ni=0; ni<8; ni++)
            mma16816(acc[mi][ni], afr[ks2][mi], bfr[ni]);
      }
    }
  }
}

// Fused key+receptance GEMM: blockIdx.x < 64 -> key (N=F), else rec (N=H)
__global__ __launch_bounds__(NTHR,2) void k_gemm_kr(){
  extern __shared__ __align__(128) __nv_bfloat16 smem[];

  const bool iskey = (blockIdx.x < 64);
  const int bm = blockIdx.y*BM;
  const int bn = (iskey ? blockIdx.x : (blockIdx.x - 64))*BM;
  const int Ndim = iskey ? F_ : H_;

  const __nv_bfloat16* A  = iskey ? g_aK  : g_aR;
  const __nv_bfloat16* Bw = iskey ? g_wkq : g_wrq;
  const float* rowscale   = iskey ? g_sK  : g_sR;
  float* C                = iskey ? g_kraw : g_rbuf;
  const float wdeq = g_wdeq[iskey ? 0 : 1];

  float acc[4][8][4];
  #pragma unroll
  for(int a0=0;a0<4;a0++)
    #pragma unroll
    for(int b0=0;b0<8;b0++)
      #pragma unroll
      for(int c0=0;c0<4;c0++) acc[a0][b0][c0]=0.f;

  gemm_main<H_>(A, Bw, bm, bn, smem, acc);

  const int warp = threadIdx.x >> 5, lane = threadIdx.x & 31;
  const int wm = (warp & 1) * 64, wn = (warp >> 1) * 64;
  const int g = lane >> 2, q = lane & 3;

  #pragma unroll
  for(int mi=0; mi<4; mi++){
    int r0 = bm + wm + mi*16 + g;
    int r1 = r0 + 8;
    float sc0 = rowscale[r0]*wdeq;
    float sc1 = rowscale[r1]*wdeq;
    #pragma unroll
    for(int ni=0; ni<8; ni++){
      int col = bn + wn + ni*8 + 2*q;
      float x0 = acc[mi][ni][0]*sc0, x1 = acc[mi][ni][1]*sc0;
      float x2 = acc[mi][ni][2]*sc1, x3 = acc[mi][ni][3]*sc1;
      if(iskey){
        x0 = (x0>0.f)? x0*x0 : 0.f;  x1 = (x1>0.f)? x1*x1 : 0.f;
        x2 = (x2>0.f)? x2*x2 : 0.f;  x3 = (x3>0.f)? x3*x3 : 0.f;
      } else {
        x0 = 1.f/(1.f+expf(-x0)); x1 = 1.f/(1.f+expf(-x1));
        x2 = 1.f/(1.f+expf(-x2)); x3 = 1.f/(1.f+expf(-x3));
      }
      *(float2*)&C[(size_t)r0*Ndim + col] = make_float2(x0, x1);
      *(float2*)&C[(size_t)r1*Ndim + col] = make_float2(x2, x3);
    }
  }
}

// Value GEMM: out = (aV * wvq^T) * rbuf
__global__ __launch_bounds__(NTHR,2) void k_gemm_v(float* __restrict__ Cout){
  extern __shared__ __align__(128) __nv_bfloat16 smem[];

  const int bm = blockIdx.y*BM, bn = blockIdx.x*BM;
  const float wdeq = g_wdeq[2];

  float acc[4][8][4];
  #pragma unroll
  for(int a0=0;a0<4;a0++)
    #pragma unroll
    for(int b0=0;b0<8;b0++)
      #pragma unroll
      for(int c0=0;c0<4;c0++) acc[a0][b0][c0]=0.f;

  gemm_main<F_>(g_aV, g_wvq, bm, bn, smem, acc);

  const int warp = threadIdx.x >> 5, lane = threadIdx.x & 31;
  const int wm = (warp & 1) * 64, wn = (warp >> 1) * 64;
  const int g = lane >> 2, q = lane & 3;

  #pragma unroll
  for(int mi=0; mi<4; mi++){
    int r0 = bm + wm + mi*16 + g;
    int r1 = r0 + 8;
    float sc0 = g_sV[r0]*wdeq;
    float sc1 = g_sV[r1]*wdeq;
    #pragma unroll
    for(int ni=0; ni<8; ni++){
      int col = bn + wn + ni*8 + 2*q;
      float x0 = acc[mi][ni][0]*sc0, x1 = acc[mi][ni][1]*sc0;
      float x2 = acc[mi][ni][2]*sc1, x3 = acc[mi][ni][3]*sc1;
      float2 m0 = *(const float2*)&g_rbuf[(size_t)r0*H_ + col];
      float2 m1 = *(const float2*)&g_rbuf[(size_t)r1*H_ + col];
      x0 *= m0.x; x1 *= m0.y; x2 *= m1.x; x3 *= m1.y;
      *(float2*)&Cout[(size_t)r0*H_ + col] = make_float2(x0, x1);
      *(float2*)&Cout[(size_t)r1*H_ + col] = make_float2(x2, x3);
    }
  }
}

// ---------------- launch ----------------
extern "C" void kernel_launch(void* const* d_in, const int* in_sizes, int n_in,
                              void* d_out, int out_size){
  const float* hidden = (const float*)d_in[0];
  const float* tmk    = (const float*)d_in[1];
  const float* tmr    = (const float*)d_in[2];
  const float* w_key  = (const float*)d_in[3];
  const float* w_rec  = (const float*)d_in[4];
  const float* w_val  = (const float*)d_in[5];
  const float* nk     = (const float*)d_in[6];
  const float* nr     = (const float*)d_in[7];
  const float* nv     = (const float*)d_in[8];
  float* out = (float*)d_out;

  cudaFuncSetAttribute(k_gemm_kr, cudaFuncAttributeMaxDynamicSharedMemorySize, SMEM_TOTAL);
  cudaFuncSetAttribute(k_gemm_v,  cudaFuncAttributeMaxDynamicSharedMemorySize, SMEM_TOTAL);

  // 1) weight |w| partials (all 3 weights, one launch)
  k_absum_all<<<3072,256>>>(w_key, w_rec, w_val);

  // 2) fused: ternary weight codes (+ g_wdeq) + token-shift/RMSNorm activation quant
  k_prep_all<<<9216 + M_, 256>>>(w_key, w_rec, w_val, hidden, tmk, tmr, nk, nr);

  // 3) fused key GEMM (relu^2 -> g_kraw) + receptance GEMM (sigmoid -> g_rbuf)
  k_gemm_kr<<<dim3(64 + 16, M_/BM), NTHR, SMEM_TOTAL>>>();

  // 4) RMSNorm + int8 codes for k
  k_quantK<<<M_,256>>>(nv);

  // 5) value GEMM -> * r -> out
  k_gemm_v<<<dim3(H_/BN, M_/BM), NTHR, SMEM_TOTAL>>>(out);
}

// round 14
// speedup vs baseline: 1.0777x; 1.0777x over previous
#include <cuda_runtime.h>
#include <cuda_bf16.h>
#include <cstdint>

#define B_ 4
#define T_ 2048
#define H_ 2048
#define F_ 8192
#define M_ (B_*T_)   // 8192 tokens

// ---------------- device scratch (static; no allocations) ----------------
__device__ __nv_bfloat16 g_wkq[(size_t)F_*H_];   // ternary key weight codes
__device__ __nv_bfloat16 g_wrq[(size_t)H_*H_];   // ternary receptance weight codes
__device__ __nv_bfloat16 g_wvq[(size_t)H_*F_];   // ternary value weight codes
__device__ __nv_bfloat16 g_aK[(size_t)M_*H_];    // int8 codes of key_in (as bf16)
__device__ __nv_bfloat16 g_aR[(size_t)M_*H_];    // int8 codes of rec_in
__device__ __nv_bfloat16 g_aV[(size_t)M_*F_];    // int8 codes of k
__device__ float g_kraw[(size_t)M_*F_];          // k = relu(.)^2 fp32; later: split-K partials
__device__ float g_rbuf[(size_t)M_*H_];          // sigmoid(receptance)
__device__ float g_sK[M_], g_sR[M_], g_sV[M_];   // per-row dequant scale
__device__ float g_part[3*1024];
__device__ float g_wdeq[3];                      // per-tensor dequant scale (1/ws)

// ---------------- reductions ----------------
__device__ __forceinline__ float warpSum(float v){
  #pragma unroll
  for(int o=16;o;o>>=1) v += __shfl_xor_sync(0xffffffffu, v, o);
  return v;
}
__device__ __forceinline__ float warpMax(float v){
  #pragma unroll
  for(int o=16;o;o>>=1) v = fmaxf(v, __shfl_xor_sync(0xffffffffu, v, o));
  return v;
}
__device__ __forceinline__ float blkSum(float v, float* sm){
  int t = threadIdx.x, nw = blockDim.x >> 5;
  v = warpSum(v);
  if((t&31)==0) sm[t>>5] = v;
  __syncthreads();
  float r = (t < nw) ? sm[t] : 0.f;
  r = warpSum(r);
  if(t==0) sm[0] = r;
  __syncthreads();
  r = sm[0];
  __syncthreads();
  return r;
}
__device__ __forceinline__ float blkMax(float v, float* sm){
  int t = threadIdx.x, nw = blockDim.x >> 5;
  v = warpMax(v);
  if((t&31)==0) sm[t>>5] = v;
  __syncthreads();
  float r = (t < nw) ? sm[t] : 0.f;
  r = warpMax(r);
  if(t==0) sm[0] = r;
  __syncthreads();
  r = sm[0];
  __syncthreads();
  return r;
}

// ---------------- weight |w| partial sums: all 3 weights in one launch ----------------
__global__ void k_absum_all(const float* __restrict__ wk, const float* __restrict__ wr,
                            const float* __restrict__ wv){
  __shared__ float sm[32];
  int region = blockIdx.x >> 10;           // 0..2
  int lb     = blockIdx.x & 1023;
  const float* w = (region==0) ? wk : (region==1) ? wr : wv;
  int n4 = (region==0) ? (F_*H_)/4 : (region==1) ? (H_*H_)/4 : (H_*F_)/4;
  float s = 0.f;
  const float4* w4 = (const float4*)w;
  for(int i = lb*blockDim.x + threadIdx.x; i < n4; i += 1024*blockDim.x){
    float4 v = w4[i];
    s += fabsf(v.x) + fabsf(v.y) + fabsf(v.z) + fabsf(v.w);
  }
  s = blkSum(s, sm);
  if(threadIdx.x == 0) g_part[region*1024 + lb] = s;
}

// ---------------- fused: ternary weight quant + token-shift/RMSNorm act quant -------
// blocks [0, 9216): weight quant; blocks [9216, 9216+M_): actprep (vectorized)
__global__ void k_prep_all(const float* __restrict__ wk, const float* __restrict__ wr,
                           const float* __restrict__ wv,
                           const float* __restrict__ hidden,
                           const float* __restrict__ tmk, const float* __restrict__ tmr,
                           const float* __restrict__ nk,  const float* __restrict__ nr){
  __shared__ float sm[32];
  int b = blockIdx.x;
  if(b < 9216){
    int region, lb, nblk;
    if(b < 4096){ region=0; lb=b; nblk=4096; }
    else if(b < 5120){ region=1; lb=b-4096; nblk=1024; }
    else { region=2; lb=b-5120; nblk=4096; }
    const float* w = (region==0) ? wk : (region==1) ? wr : wv;
    __nv_bfloat16* wq = (region==0) ? g_wkq : (region==1) ? g_wrq : g_wvq;
    int n4 = (region==0) ? (F_*H_)/4 : (region==1) ? (H_*H_)/4 : (H_*F_)/4;
    float cnt = (float)((size_t)n4*4);

    float p = 0.f;
    #pragma unroll
    for(int j=0;j<4;j++) p += g_part[region*1024 + threadIdx.x + j*256];
    float tot = blkSum(p, sm);
    float wdeq = fmaxf(tot/cnt, 1e-5f);
    float ws = 1.f / wdeq;
    if(lb == 0 && threadIdx.x == 0) g_wdeq[region] = wdeq;

    for(int i = lb*blockDim.x + threadIdx.x; i < n4; i += nblk*blockDim.x){
      float4 v = ((const float4*)w)[i];
      float q0 = fminf(fmaxf(rintf(v.x*ws), -1.f), 1.f);
      float q1 = fminf(fmaxf(rintf(v.y*ws), -1.f), 1.f);
      float q2 = fminf(fmaxf(rintf(v.z*ws), -1.f), 1.f);
      float q3 = fminf(fmaxf(rintf(v.w*ws), -1.f), 1.f);
      __nv_bfloat162* o = ((__nv_bfloat162*)wq) + 2*(size_t)i;
      o[0] = __floats2bfloat162_rn(q0, q1);
      o[1] = __floats2bfloat162_rn(q2, q3);
    }
  } else {
    int m = b - 9216;
    int t = m & (T_-1);
    const float4* cur  = (const float4*)(hidden + (size_t)m*H_);
    const float4* tmk4 = (const float4*)tmk;
    const float4* tmr4 = (const float4*)tmr;
    const float4* nk4  = (const float4*)nk;
    const float4* nr4  = (const float4*)nr;
    const int base = threadIdx.x*2;                 // 2 float4 = 8 contiguous elems
    float4 kin[2], rin[2];
    float ssk=0.f, ssr=0.f, amk=0.f, amr=0.f;
    #pragma unroll
    for(int j=0;j<2;j++){
      float4 xc = cur[base+j];
      float4 xp = (t==0) ? make_float4(0.f,0.f,0.f,0.f) : cur[base+j - H_/4];
      float4 a = tmk4[base+j], bb = tmr4[base+j];
      float4 wkv = nk4[base+j], wrv = nr4[base+j];
      float4 ki, ri;
      ki.x = xc.x*a.x + xp.x*(1.f-a.x);  ki.y = xc.y*a.y + xp.y*(1.f-a.y);
      ki.z = xc.z*a.z + xp.z*(1.f-a.z);  ki.w = xc.w*a.w + xp.w*(1.f-a.w);
      ri.x = xc.x*bb.x + xp.x*(1.f-bb.x); ri.y = xc.y*bb.y + xp.y*(1.f-bb.y);
      ri.z = xc.z*bb.z + xp.z*(1.f-bb.z); ri.w = xc.w*bb.w + xp.w*(1.f-bb.w);
      kin[j]=ki; rin[j]=ri;
      ssk += ki.x*ki.x + ki.y*ki.y + ki.z*ki.z + ki.w*ki.w;
      ssr += ri.x*ri.x + ri.y*ri.y + ri.z*ri.z + ri.w*ri.w;
      amk = fmaxf(amk, fmaxf(fmaxf(fabsf(ki.x*wkv.x), fabsf(ki.y*wkv.y)),
                             fmaxf(fabsf(ki.z*wkv.z), fabsf(ki.w*wkv.w))));
      amr = fmaxf(amr, fmaxf(fmaxf(fabsf(ri.x*wrv.x), fabsf(ri.y*wrv.y)),
                             fmaxf(fabsf(ri.z*wrv.z), fabsf(ri.w*wrv.w))));
    }
    float tssk = blkSum(ssk, sm);
    float tssr = blkSum(ssr, sm);
    float tamk = blkMax(amk, sm);
    float tamr = blkMax(amr, sm);
    float rk = rsqrtf(tssk*(1.f/H_) + 1e-8f);
    float rr = rsqrtf(tssr*(1.f/H_) + 1e-8f);
    float rsK = fmaxf(tamk*rk, 1e-5f);
    float rsR = fmaxf(tamr*rr, 1e-5f);
    float sk = 127.f/rsK, sr = 127.f/rsR;
    uint32_t pk[4], pr[4];
    #pragma unroll
    for(int j=0;j<2;j++){
      float4 wkv = nk4[base+j], wrv = nr4[base+j];
      float4 ki = kin[j], ri = rin[j];
      float qk0 = fminf(fmaxf(rintf(ki.x*wkv.x*rk*sk), -128.f), 127.f);
      float qk1 = fminf(fmaxf(rintf(ki.y*wkv.y*rk*sk), -128.f), 127.f);
      float qk2 = fminf(fmaxf(rintf(ki.z*wkv.z*rk*sk), -128.f), 127.f);
      float qk3 = fminf(fmaxf(rintf(ki.w*wkv.w*rk*sk), -128.f), 127.f);
      float qr0 = fminf(fmaxf(rintf(ri.x*wrv.x*rr*sr), -128.f), 127.f);
      float qr1 = fminf(fmaxf(rintf(ri.y*wrv.y*rr*sr), -128.f), 127.f);
      float qr2 = fminf(fmaxf(rintf(ri.z*wrv.z*rr*sr), -128.f), 127.f);
      float qr3 = fminf(fmaxf(rintf(ri.w*wrv.w*rr*sr), -128.f), 127.f);
      __nv_bfloat162 k01 = __floats2bfloat162_rn(qk0, qk1);
      __nv_bfloat162 k23 = __floats2bfloat162_rn(qk2, qk3);
      __nv_bfloat162 r01 = __floats2bfloat162_rn(qr0, qr1);
      __nv_bfloat162 r23 = __floats2bfloat162_rn(qr2, qr3);
      pk[2*j]   = *(uint32_t*)&k01;  pk[2*j+1] = *(uint32_t*)&k23;
      pr[2*j]   = *(uint32_t*)&r01;  pr[2*j+1] = *(uint32_t*)&r23;
    }
    *((uint4*)(g_aK + (size_t)m*H_) + threadIdx.x) = make_uint4(pk[0],pk[1],pk[2],pk[3]);
    *((uint4*)(g_aR + (size_t)m*H_) + threadIdx.x) = make_uint4(pr[0],pr[1],pr[2],pr[3]);
    if(threadIdx.x == 0){ g_sK[m] = rsK*(1.f/127.f); g_sR[m] = rsR*(1.f/127.f); }
  }
}

// ---------------- RMSNorm + int8 quant of k rows (F=8192), vectorized ----------------
__global__ void k_quantK(const float* __restrict__ nv){
  __shared__ float sm[32];
  int m = blockIdx.x;
  const float4* row = (const float4*)(g_kraw + (size_t)m*F_);
  const float4* nv4 = (const float4*)nv;
  float4 v[8];
  float ss=0.f, am=0.f;
  #pragma unroll
  for(int j=0;j<8;j++){
    float4 x = row[threadIdx.x + j*256];
    float4 n = nv4[threadIdx.x + j*256];
    v[j] = x;
    ss += x.x*x.x + x.y*x.y + x.z*x.z + x.w*x.w;
    am = fmaxf(am, fmaxf(fmaxf(fabsf(x.x*n.x), fabsf(x.y*n.y)),
                         fmaxf(fabsf(x.z*n.z), fabsf(x.w*n.w))));
  }
  float tss = blkSum(ss, sm);
  float tam = blkMax(am, sm);
  float rinv = rsqrtf(tss*(1.f/F_) + 1e-8f);
  float rs = fmaxf(tam*rinv, 1e-5f);
  float s = 127.f/rs;
  #pragma unroll
  for(int j=0;j<8;j++){
    float4 n = nv4[threadIdx.x + j*256];
    float4 x = v[j];
    float q0 = fminf(fmaxf(rintf(x.x*n.x*rinv*s), -128.f), 127.f);
    float q1 = fminf(fmaxf(rintf(x.y*n.y*rinv*s), -128.f), 127.f);
    float q2 = fminf(fmaxf(rintf(x.z*n.z*rinv*s), -128.f), 127.f);
    float q3 = fminf(fmaxf(rintf(x.w*n.w*rinv*s), -128.f), 127.f);
    __nv_bfloat162 c01 = __floats2bfloat162_rn(q0, q1);
    __nv_bfloat162 c23 = __floats2bfloat162_rn(q2, q3);
    uint2 pk = make_uint2(*(uint32_t*)&c01, *(uint32_t*)&c23);
    *((uint2*)(g_aV + (size_t)m*F_) + threadIdx.x + j*256) = pk;
  }
  if(threadIdx.x == 0) g_sV[m] = rs*(1.f/127.f);
}

// ---------------- bf16 tensor-core GEMM ----------------
#define BM 128
#define BN 128
#define BKg 64          // 64 bf16 elems = 128 B per row
#define LDT 72          // elems: 64 + 8 pad -> 144B row stride, conflict-free
#define NSTAGE 3
#define NTHR 128
#define STAGE_E ((BM+BN)*LDT)           // elems per stage: 18432
#define STAGE_BYTES (STAGE_E*2)         // 36864 B
#define SMEM_TOTAL (NSTAGE*STAGE_BYTES) // 110592 B

__device__ __forceinline__ void cp16(uint32_t s, const void* g){
  asm volatile("cp.async.cg.shared.global [%0], [%1], 16;" :: "r"(s), "l"(g));
}
__device__ __forceinline__ void cp_commit(){ asm volatile("cp.async.commit_group;" ::: "memory"); }
template<int N> __device__ __forceinline__ void cp_wait(){
  asm volatile("cp.async.wait_group %0;" :: "n"(N) : "memory");
}
__device__ __forceinline__ void ldsm4(uint32_t& r0, uint32_t& r1, uint32_t& r2, uint32_t& r3,
                                      uint32_t addr){
  asm volatile("ldmatrix.sync.aligned.m8n8.x4.shared.b16 {%0,%1,%2,%3}, [%4];"
               : "=r"(r0), "=r"(r1), "=r"(r2), "=r"(r3) : "r"(addr));
}
__device__ __forceinline__ void mma16816(float* c, const uint32_t* a, const uint32_t* b){
  asm volatile(
    "mma.sync.aligned.m16n8k16.row.col.f32.bf16.bf16.f32 "
    "{%0,%1,%2,%3}, {%4,%5,%6,%7}, {%8,%9}, {%0,%1,%2,%3};\n"
    : "+f"(c[0]), "+f"(c[1]), "+f"(c[2]), "+f"(c[3])
    : "r"(a[0]), "r"(a[1]), "r"(a[2]), "r"(a[3]), "r"(b[0]), "r"(b[1]));
}

// Shared mainloop over kt in [kt0, kt0+nkt): acc += A[bm:,:]*Bw[bn:,:]^T
template<int KDIM>
__device__ __forceinline__ void gemm_main(const __nv_bfloat16* __restrict__ A,
                                          const __nv_bfloat16* __restrict__ Bw,
                                          int bm, int bn, int kt0, int nkt,
                                          __nv_bfloat16* smem,
                                          float acc[4][8][4]){
  const int tid = threadIdx.x;

  auto loads = [&](int buf, int kt){
    __nv_bfloat16* st = smem + buf*STAGE_E;
    const __nv_bfloat16* Ak = A  + (size_t)bm*KDIM + kt*BKg;
    const __nv_bfloat16* Bk = Bw + (size_t)bn*KDIM + kt*BKg;
    #pragma unroll
    for(int i=0;i<16;i++){
      int chunk = tid + NTHR*i;        // 0..2047 : 256 rows x 8 x 16B
      int row = chunk >> 3;
      int kc  = (chunk & 7) << 3;      // elems: 0,8,...,56
      const __nv_bfloat16* gp = (row < BM) ? (Ak + (size_t)row*KDIM + kc)
                                           : (Bk + (size_t)(row-BM)*KDIM + kc);
      cp16((uint32_t)__cvta_generic_to_shared(st + row*LDT + kc), gp);
    }
    cp_commit();
  };

  const int warp = tid >> 5, lane = tid & 31;
  const int wm = (warp & 1) * 64;
  const int wn = (warp >> 1) * 64;

  const uint32_t sbu = (uint32_t)__cvta_generic_to_shared(smem);
  const int aoff = (wm + (lane & 15))*LDT + ((lane >> 4) << 3);
  const int boff = (wn + (lane & 7) + ((lane >> 4) << 3))*LDT + (((lane >> 3) & 1) << 3);

  loads(0, kt0);
  loads(1, kt0 + 1);

  #pragma unroll 1
  for(int kt=0; kt<nkt; kt++){
    cp_wait<NSTAGE-2>();
    __syncthreads();
    if(kt + NSTAGE - 1 < nkt) loads((kt + NSTAGE - 1) % NSTAGE, kt0 + kt + NSTAGE - 1);
    else cp_commit();

    const int buf = kt % NSTAGE;
    const uint32_t abase = sbu + buf*STAGE_BYTES;
    const uint32_t bbase = abase + BM*LDT*2;

    // ks pairs: batch A-fragment ldsm for 2 ks steps, then per-ks B ldsm + mma
    #pragma unroll
    for(int kp=0; kp<2; kp++){
      uint32_t afr[2][4][4];
      #pragma unroll
      for(int ks2=0; ks2<2; ks2++){
        const int kk = (kp*2 + ks2)*16;
        #pragma unroll
        for(int mi=0; mi<4; mi++)
          ldsm4(afr[ks2][mi][0], afr[ks2][mi][1], afr[ks2][mi][2], afr[ks2][mi][3],
                abase + (uint32_t)(aoff + mi*16*LDT + kk)*2);
      }
      #pragma unroll
      for(int ks2=0; ks2<2; ks2++){
        const int kk = (kp*2 + ks2)*16;
        uint32_t bfr[8][2];
        #pragma unroll
        for(int nip=0; nip<4; nip++)
          ldsm4(bfr[2*nip][0], bfr[2*nip][1], bfr[2*nip+1][0], bfr[2*nip+1][1],
                bbase + (uint32_t)(boff + nip*16*LDT + kk)*2);
        #pragma unroll
        for(int mi=0; mi<4; mi++)
          #pragma unroll
          for(int ni=0; ni<8; ni++)
            mma16816(acc[mi][ni], afr[ks2][mi], bfr[ni]);
      }
    }
  }
}

// Fused key+receptance GEMM: blockIdx.x < 64 -> key (N=F), else rec (N=H)
__global__ __launch_bounds__(NTHR,2) void k_gemm_kr(){
  extern __shared__ __align__(128) __nv_bfloat16 smem[];

  const bool iskey = (blockIdx.x < 64);
  const int bm = blockIdx.y*BM;
  const int bn = (iskey ? blockIdx.x : (blockIdx.x - 64))*BM;
  const int Ndim = iskey ? F_ : H_;

  const __nv_bfloat16* A  = iskey ? g_aK  : g_aR;
  const __nv_bfloat16* Bw = iskey ? g_wkq : g_wrq;
  const float* rowscale   = iskey ? g_sK  : g_sR;
  float* C                = iskey ? g_kraw : g_rbuf;
  const float wdeq = g_wdeq[iskey ? 0 : 1];

  float acc[4][8][4];
  #pragma unroll
  for(int a0=0;a0<4;a0++)
    #pragma unroll
    for(int b0=0;b0<8;b0++)
      #pragma unroll
      for(int c0=0;c0<4;c0++) acc[a0][b0][c0]=0.f;

  gemm_main<H_>(A, Bw, bm, bn, 0, H_/BKg, smem, acc);

  const int warp = threadIdx.x >> 5, lane = threadIdx.x & 31;
  const int wm = (warp & 1) * 64, wn = (warp >> 1) * 64;
  const int g = lane >> 2, q = lane & 3;

  #pragma unroll
  for(int mi=0; mi<4; mi++){
    int r0 = bm + wm + mi*16 + g;
    int r1 = r0 + 8;
    float sc0 = rowscale[r0]*wdeq;
    float sc1 = rowscale[r1]*wdeq;
    #pragma unroll
    for(int ni=0; ni<8; ni++){
      int col = bn + wn + ni*8 + 2*q;
      float x0 = acc[mi][ni][0]*sc0, x1 = acc[mi][ni][1]*sc0;
      float x2 = acc[mi][ni][2]*sc1, x3 = acc[mi][ni][3]*sc1;
      if(iskey){
        x0 = (x0>0.f)? x0*x0 : 0.f;  x1 = (x1>0.f)? x1*x1 : 0.f;
        x2 = (x2>0.f)? x2*x2 : 0.f;  x3 = (x3>0.f)? x3*x3 : 0.f;
      } else {
        x0 = 1.f/(1.f+expf(-x0)); x1 = 1.f/(1.f+expf(-x1));
        x2 = 1.f/(1.f+expf(-x2)); x3 = 1.f/(1.f+expf(-x3));
      }
      *(float2*)&C[(size_t)r0*Ndim + col] = make_float2(x0, x1);
      *(float2*)&C[(size_t)r1*Ndim + col] = make_float2(x2, x3);
    }
  }
}

// Value GEMM, split-K=2: blockIdx.z = K-half; raw partial sums into g_kraw scratch.
// Partials are exact integer sums in fp32, so p0+p1 is bit-identical to unsplit.
__global__ __launch_bounds__(NTHR,2) void k_gemm_v(){
  extern __shared__ __align__(128) __nv_bfloat16 smem[];

  const int bm = blockIdx.y*BM, bn = blockIdx.x*BM;
  const int half = blockIdx.z;
  constexpr int HKT = (F_/BKg)/2;   // 64 k-tiles per half

  float acc[4][8][4];
  #pragma unroll
  for(int a0=0;a0<4;a0++)
    #pragma unroll
    for(int b0=0;b0<8;b0++)
      #pragma unroll
      for(int c0=0;c0<4;c0++) acc[a0][b0][c0]=0.f;

  gemm_main<F_>(g_aV, g_wvq, bm, bn, half*HKT, HKT, smem, acc);

  float* P = g_kraw + (size_t)half*M_*H_;
  const int warp = threadIdx.x >> 5, lane = threadIdx.x & 31;
  const int wm = (warp & 1) * 64, wn = (warp >> 1) * 64;
  const int g = lane >> 2, q = lane & 3;

  #pragma unroll
  for(int mi=0; mi<4; mi++){
    int r0 = bm + wm + mi*16 + g;
    int r1 = r0 + 8;
    #pragma unroll
    for(int ni=0; ni<8; ni++){
      int col = bn + wn + ni*8 + 2*q;
      *(float2*)&P[(size_t)r0*H_ + col] = make_float2(acc[mi][ni][0], acc[mi][ni][1]);
      *(float2*)&P[(size_t)r1*H_ + col] = make_float2(acc[mi][ni][2], acc[mi][ni][3]);
    }
  }
}

// Reduce split-K partials: out = (p0+p1) * sV[m] * wdeq * r
__global__ void k_vred(float* __restrict__ out){
  size_t i = (size_t)blockIdx.x*256 + threadIdx.x;     // float4 index; total M_*H_/4
  const float4* P0 = (const float4*)g_kraw;
  const float4* P1 = P0 + (size_t)M_*H_/4;
  float4 p0 = P0[i];
  float4 p1 = P1[i];
  int m = (int)(i / (H_/4));
  float sc = g_sV[m]*g_wdeq[2];
  float4 r = ((const float4*)g_rbuf)[i];
  float4 o;
  o.x = (p0.x+p1.x)*sc*r.x;
  o.y = (p0.y+p1.y)*sc*r.y;
  o.z = (p0.z+p1.z)*sc*r.z;
  o.w = (p0.w+p1.w)*sc*r.w;
  ((float4*)out)[i] = o;
}

// ---------------- launch ----------------
extern "C" void kernel_launch(void* const* d_in, const int* in_sizes, int n_in,
                              void* d_out, int out_size){
  const float* hidden = (const float*)d_in[0];
  const float* tmk    = (const float*)d_in[1];
  const float* tmr    = (const float*)d_in[2];
  const float* w_key  = (const float*)d_in[3];
  const float* w_rec  = (const float*)d_in[4];
  const float* w_val  = (const float*)d_in[5];
  const float* nk     = (const float*)d_in[6];
  const float* nr     = (const float*)d_in[7];
  const float* nv     = (const float*)d_in[8];
  float* out = (float*)d_out;

  cudaFuncSetAttribute(k_gemm_kr, cudaFuncAttributeMaxDynamicSharedMemorySize, SMEM_TOTAL);
  cudaFuncSetAttribute(k_gemm_v,  cudaFuncAttributeMaxDynamicSharedMemorySize, SMEM_TOTAL);

  // 1) weight |w| partials (all 3 weights, one launch)
  k_absum_all<<<3072,256>>>(w_key, w_rec, w_val);

  // 2) fused: ternary weight codes (+ g_wdeq) + token-shift/RMSNorm activation quant
  k_prep_all<<<9216 + M_, 256>>>(w_key, w_rec, w_val, hidden, tmk, tmr, nk, nr);

  // 3) fused key GEMM (relu^2 -> g_kraw) + receptance GEMM (sigmoid -> g_rbuf)
  k_gemm_kr<<<dim3(64 + 16, M_/BM), NTHR, SMEM_TOTAL>>>();

  // 4) RMSNorm + int8 codes for k
  k_quantK<<<M_,256>>>(nv);

  // 5) value GEMM split-K=2 -> raw partials in g_kraw scratch
  k_gemm_v<<<dim3(H_/BN, M_/BM, 2), NTHR, SMEM_TOTAL>>>();

  // 6) reduce partials, apply scales and * r -> out
  k_vred<<<(M_*H_/4)/256, 256>>>(out);
}